// round 17
// baseline (speedup 1.0000x reference)
#include <cuda_runtime.h>
#include <cuda_fp16.h>
#include <math.h>
#include <stdint.h>

// Problem constants: B=2, C=256, N=65536.
#define NE 65536
#define NB 2

// ---------------- scratch (device globals; no allocations) ----------------
__device__ __align__(16) __half g_XtH[(size_t)NB * NE * 128];   // x_all transposed fp16 [b][e][c]
__device__ __align__(16) __half g_preH[(size_t)NB * 512 * NE];  // pre-activations fp16 [b][r][e]
__device__ __align__(16) __half g_Wh[5 * 512 * 128];            // folded W fp16
__device__ __align__(16) __half g_W1h[2 * 64 * 256];            // stage1 weights fp16 [half][r][k]
__device__ float g_Cf[512];
__device__ float g_S[NB * 512];
__device__ float g_S2[NB * 512];

// ================= helpers =================
__device__ __forceinline__ uint32_t smem_u32(const void* p) {
    uint32_t a;
    asm("{ .reg .u64 t; cvta.to.shared.u64 t, %1; cvt.u32.u64 %0, t; }" : "=r"(a) : "l"(p));
    return a;
}
__device__ __forceinline__ void ldsm4(uint32_t* r, uint32_t addr) {
    asm volatile("ldmatrix.sync.aligned.m8n8.x4.shared.b16 {%0, %1, %2, %3}, [%4];"
                 : "=r"(r[0]), "=r"(r[1]), "=r"(r[2]), "=r"(r[3]) : "r"(addr));
}
__device__ __forceinline__ void ldsm2(uint32_t* r, uint32_t addr) {
    asm volatile("ldmatrix.sync.aligned.m8n8.x2.shared.b16 {%0, %1}, [%2];"
                 : "=r"(r[0]), "=r"(r[1]) : "r"(addr));
}
__device__ __forceinline__ void mma_f16(float* d, const uint32_t* a, const uint32_t* b) {
    asm volatile(
        "mma.sync.aligned.m16n8k16.row.col.f32.f16.f16.f32 "
        "{%0,%1,%2,%3}, {%4,%5,%6,%7}, {%8,%9}, {%0,%1,%2,%3};"
        : "+f"(d[0]), "+f"(d[1]), "+f"(d[2]), "+f"(d[3])
        : "r"(a[0]), "r"(a[1]), "r"(a[2]), "r"(a[3]), "r"(b[0]), "r"(b[1]));
}
#define CPA(dst, src) \
    asm volatile("cp.async.ca.shared.global [%0], [%1], 16;" :: "r"(dst), "l"(src))
#define CPA_COMMIT() asm volatile("cp.async.commit_group;" ::: "memory")
#define CPA_WAIT() asm volatile("cp.async.wait_group 0;" ::: "memory")

// pack 8 floats -> 8 fp16 (one uint4)
__device__ __forceinline__ uint4 pack8h(const float* f) {
    uint4 o;
    __half2 h;
    h = __floats2half2_rn(f[0], f[1]); o.x = *reinterpret_cast<unsigned*>(&h);
    h = __floats2half2_rn(f[2], f[3]); o.y = *reinterpret_cast<unsigned*>(&h);
    h = __floats2half2_rn(f[4], f[5]); o.z = *reinterpret_cast<unsigned*>(&h);
    h = __floats2half2_rn(f[6], f[7]); o.w = *reinterpret_cast<unsigned*>(&h);
    return o;
}

// ---------------- kernel 0a: fold weight matrices (emit fp16) ----------------
__global__ void fold_w_kernel(const float* __restrict__ Waf, const float* __restrict__ Wal,
                              const float* __restrict__ Wat,
                              const float* __restrict__ Wbf, const float* __restrict__ Wbl,
                              const float* __restrict__ Wbt) {
    int r = blockIdx.x;
    int c = threadIdx.x;
    const float *F, *L, *T;
    if (r < 256) { F = Waf; L = Wal; T = Wat; } else { F = Wbf; L = Wbl; T = Wbt; }
    int rr = r & 255;
    float a[5] = {0.f, 0.f, 0.f, 0.f, 0.f};
    for (int j = 0; j < 128; j++) {
        float fl = F[rr * 256 + j];
        float fr = F[rr * 256 + 128 + j];
        a[0] += fl * L[j * 128 + c];
        const float* t = &T[(j * 128 + c) * 5];
        a[0] += fr * t[0];
        a[1] += fr * t[1];
        a[2] += fr * t[2];
        a[3] += fr * t[3];
        a[4] += fr * t[4];
    }
#pragma unroll
    for (int g = 0; g < 5; g++)
        g_Wh[(g * 512 + r) * 128 + c] = __float2half_rn(a[g]);
}

// ---------------- kernel 0b: fold bias (parallel) + zero stats accumulators ----------------
__global__ void fold_c_kernel(const float* __restrict__ Waf, const float* __restrict__ bal,
                              const float* __restrict__ bat, const float* __restrict__ baf,
                              const float* __restrict__ Wbf, const float* __restrict__ bbl,
                              const float* __restrict__ bbt, const float* __restrict__ bbf) {
    int r = blockIdx.x;   // 0..511
    int t = threadIdx.x;  // 0..127
    const float *F, *lb, *tb, *fb;
    if (r < 256) { F = Waf; lb = bal; tb = bat; fb = baf; }
    else         { F = Wbf; lb = bbl; tb = bbt; fb = bbf; }
    int rr = r & 255;
    float s = F[rr * 256 + t] * lb[t] + F[rr * 256 + 128 + t] * tb[t];
    __shared__ float red[128];
    red[t] = s;
    __syncthreads();
    for (int st = 64; st > 0; st >>= 1) {
        if (t < st) red[t] += red[t + st];
        __syncthreads();
    }
    if (t == 0) {
        g_Cf[r] = red[0] + fb[rr];
        g_S[r] = 0.f; g_S[r + 512] = 0.f;
        g_S2[r] = 0.f; g_S2[r + 512] = 0.f;
    }
}

// ---------------- kernel 0c: convert stage1 weights to fp16 ----------------
__global__ void conv_w1_kernel(const float* __restrict__ Wa, const float* __restrict__ Wb) {
    int i = blockIdx.x * 256 + threadIdx.x;  // 0..32767
    const float* src = (i < 16384) ? Wa : Wb;
    g_W1h[i] = __float2half_rn(src[i & 16383]);
}

// ---------------- kernel 1: x_all via mma.sync fp16, cp.async staged x ----------------
// Block 256 (8 warps 2x4). Tile M=64 rows x N=128 edges, K=256 in 4 chunks of 64.
// x chunks staged fp32 via cp.async -> smem convert pass -> fp16 B buffers.
#define S1_AH  0            // 64 x 528B = 33792
#define S1_B0  33792        // 128 x 144B = 18432
#define S1_B1  52224
#define S1_XF  70656        // 64 x 512B fp32 staging = 32768
#define S1_TOT 103424

__global__ __launch_bounds__(256) void stage1_kernel(
    const float* __restrict__ x0, const float* __restrict__ x1,
    const float* __restrict__ ba, const float* __restrict__ bb) {
    extern __shared__ char sm1[];
    uint32_t sb = smem_u32(sm1);
    int tid = threadIdx.x;
    int lane = tid & 31, wid = tid >> 5;
    int wm = wid >> 2, wn = wid & 3;
    int e0 = blockIdx.x * 128;
    int b = blockIdx.y, half = blockIdx.z;
    const float* X = ((half == 0) ? x0 : x1) + (size_t)b * 256 * NE;
    const float* bias = (half == 0) ? ba : bb;

    int eIdx = tid & 127;
    int kbase = (tid >> 7) * 32;

    float acc[2][4][4];
#pragma unroll
    for (int mi = 0; mi < 2; mi++)
#pragma unroll
        for (int ni = 0; ni < 4; ni++)
#pragma unroll
            for (int j = 0; j < 4; j++) acc[mi][ni][j] = 0.f;

    uint32_t aOff = (uint32_t)((wm * 32 + (lane & 15)) * 528 + (lane >> 4) * 16);
    uint32_t bOff = (uint32_t)((wn * 32 + (lane & 7)) * 144 + ((lane >> 3) & 1) * 16);

#define S1_CPX(KC)                                                                    \
    {                                                                                 \
        for (int i = tid; i < 2048; i += 256) {                                       \
            int row_ = i >> 5, seg_ = i & 31;                                         \
            CPA(sb + S1_XF + row_ * 512 + seg_ * 16,                                  \
                X + (size_t)((KC) * 64 + row_) * NE + e0 + seg_ * 4);                 \
        }                                                                             \
        CPA_COMMIT();                                                                 \
    }
#define S1_CONV(BH)                                                                   \
    {                                                                                 \
        const float* Xf_ = (const float*)(sm1 + S1_XF);                               \
        _Pragma("unroll") for (int g = 0; g < 4; g++) {                               \
            float f_[8];                                                              \
            int k0_ = kbase + g * 8;                                                  \
            _Pragma("unroll") for (int j = 0; j < 8; j++)                             \
                f_[j] = Xf_[(k0_ + j) * 128 + eIdx];                                  \
            *(uint4*)(sm1 + (BH) + eIdx * 144 + k0_ * 2) = pack8h(f_);                \
        }                                                                             \
    }
#define S1_MMA(BH, KC, KK)                                                            \
    {                                                                                 \
        uint32_t ah_[2][4], bh_[4][2];                                                \
        _Pragma("unroll") for (int mi = 0; mi < 2; mi++)                              \
            ldsm4(ah_[mi], sb + S1_AH + aOff + mi * (16 * 528) + (KC) * 128 + (KK) * 32); \
        _Pragma("unroll") for (int ni = 0; ni < 4; ni++)                              \
            ldsm2(bh_[ni], sb + (BH) + bOff + ni * (8 * 144) + (KK) * 32);            \
        _Pragma("unroll") for (int mi = 0; mi < 2; mi++)                              \
            _Pragma("unroll") for (int ni = 0; ni < 4; ni++)                          \
                mma_f16(acc[mi][ni], ah_[mi], bh_[ni]);                               \
    }

    // prologue: A weights (fp16) + x chunk0 via cp.async; convert chunk0 -> B0
    {
        const __half* Wh = g_W1h + (size_t)half * (64 * 256);
        for (int i = tid; i < 2048; i += 256) {
            int r = i >> 5, cq = i & 31;
            CPA(sb + S1_AH + r * 528 + cq * 16, Wh + r * 256 + cq * 8);
        }
    }
    S1_CPX(0);
    CPA_WAIT();
    __syncthreads();
    S1_CONV(S1_B0);
    __syncthreads();

#pragma unroll
    for (int kc = 0; kc < 4; kc++) {
        uint32_t BH = (kc & 1) ? S1_B1 : S1_B0;
        uint32_t BnH = (kc & 1) ? S1_B0 : S1_B1;
        if (kc < 3) S1_CPX(kc + 1);
        S1_MMA(BH, kc, 0);
        S1_MMA(BH, kc, 1);
        S1_MMA(BH, kc, 2);
        S1_MMA(BH, kc, 3);
        if (kc < 3) {
            CPA_WAIT();
            __syncthreads();
            S1_CONV(BnH);
        }
        __syncthreads();
    }

    // epilogue: bias, transpose through smem (fp32), pack fp16, coalesced store
    float* T = (float*)(sm1 + S1_B0);  // [r][e] stride 132 floats (fits B0+B1)
#pragma unroll
    for (int mi = 0; mi < 2; mi++) {
        int r0 = wm * 32 + mi * 16 + (lane >> 2);
        int r1 = r0 + 8;
        float c0 = bias[r0], c1 = bias[r1];
#pragma unroll
        for (int ni = 0; ni < 4; ni++) {
            int ecol = wn * 32 + ni * 8 + (lane & 3) * 2;
            T[r0 * 132 + ecol] = acc[mi][ni][0] + c0;
            T[r0 * 132 + ecol + 1] = acc[mi][ni][1] + c0;
            T[r1 * 132 + ecol] = acc[mi][ni][2] + c1;
            T[r1 * 132 + ecol + 1] = acc[mi][ni][3] + c1;
        }
    }
    __syncthreads();
    __half* dst = g_XtH + (size_t)b * NE * 128;
    for (int i = tid; i < 1024; i += 256) {
        int e = i >> 3, seg = i & 7;
        float v[8];
#pragma unroll
        for (int j = 0; j < 8; j++) v[j] = T[(seg * 8 + j) * 132 + e];
        *(uint4*)&dst[(size_t)(e0 + e) * 128 + half * 64 + seg * 8] = pack8h(v);
    }
}

// ---------------- kernel 2: pipelined fused GEMM + stats (fp16, M=256 tile) ----------------
#define SM_NIDX 0
#define SM_A0   2048
#define SM_A1   38912
#define SM_BA   75776
#define SM_BB   110592
#define SM_BC   145408
#define SM_BD   180224
#define SM_TOT  215040

__global__ __launch_bounds__(512, 1) void stage2_kernel(const int* __restrict__ gemm) {
    extern __shared__ char sm2[];
    uint32_t sb = smem_u32(sm2);
    int tid = threadIdx.x;
    int lane = tid & 31, wid = tid >> 5;
    int wm = wid >> 2, wn = wid & 3;
    int e0 = blockIdx.x * 128;
    int b = blockIdx.y, z = blockIdx.z;

    int4* nidx = (int4*)(sm2 + SM_NIDX);
    const __half* XtH = g_XtH + (size_t)b * NE * 128;

    float acc[4][4][4];
#pragma unroll
    for (int mi = 0; mi < 4; mi++)
#pragma unroll
        for (int ni = 0; ni < 4; ni++)
#pragma unroll
            for (int j = 0; j < 4; j++) acc[mi][ni][j] = 0.f;

    uint32_t aOff = (uint32_t)((wm * 64 + (lane & 15)) * 144 + (lane >> 4) * 16);
    uint32_t bOff = (uint32_t)((wn * 32 + ((lane >> 4) << 3) + (lane & 7)) * 272 +
                               ((lane >> 3) & 1) * 16);

#define CPA_A(G, KHP, ABASE)                                                          \
    {                                                                                 \
        const __half* s_ = g_Wh + ((size_t)(G) * 512 + z * 256) * 128 + (KHP) * 64;   \
        _Pragma("unroll") for (int i_ = 0; i_ < 4; i_++) {                            \
            int ii_ = tid + i_ * 512;                                                 \
            int row_ = ii_ >> 3, cg_ = ii_ & 7;                                       \
            CPA(sb + (ABASE) + row_ * 144 + cg_ * 16, s_ + (size_t)row_ * 128 + cg_ * 8); \
        }                                                                             \
        CPA_COMMIT();                                                                 \
    }

    uint4 ha_, hb_, hc_, hd_;
#define LDGP_A(P, IT)                                                                 \
    {                                                                                 \
        int idx_ = tid + (IT) * 512;                                                  \
        int e_ = idx_ >> 4, cq_ = idx_ & 15;                                          \
        int4 nn_ = nidx[e_];                                                          \
        int na_ = (P) ? nn_.y : nn_.x;                                                \
        int nc_ = (P) ? nn_.w : nn_.z;                                                \
        ha_ = *(const uint4*)&XtH[(size_t)na_ * 128 + cq_ * 8];                       \
        hb_ = *(const uint4*)&XtH[(size_t)nc_ * 128 + cq_ * 8];                       \
    }
#define LDGP_B(P, IT)                                                                 \
    {                                                                                 \
        int idx_ = tid + (IT) * 512;                                                  \
        int e_ = idx_ >> 4, cq_ = idx_ & 15;                                          \
        int4 nn_ = nidx[e_];                                                          \
        int na_ = (P) ? nn_.y : nn_.x;                                                \
        int nc_ = (P) ? nn_.w : nn_.z;                                                \
        hc_ = *(const uint4*)&XtH[(size_t)na_ * 128 + cq_ * 8];                       \
        hd_ = *(const uint4*)&XtH[(size_t)nc_ * 128 + cq_ * 8];                       \
    }
#define PSTP_X(SUMB, DIFB, IT, RA, RB)                                                \
    {                                                                                 \
        int idx_ = tid + (IT) * 512;                                                  \
        int e_ = idx_ >> 4, cq_ = idx_ & 15;                                          \
        uint4 so_, do_;                                                               \
        __half2* pa_ = (__half2*)&RA;                                                 \
        __half2* pb_ = (__half2*)&RB;                                                 \
        __half2* ps_ = (__half2*)&so_;                                                \
        __half2* pd_ = (__half2*)&do_;                                                \
        _Pragma("unroll") for (int j_ = 0; j_ < 4; j_++) {                            \
            ps_[j_] = __hadd2(pa_[j_], pb_[j_]);                                      \
            pd_[j_] = __habs2(__hsub2(pa_[j_], pb_[j_]));                             \
        }                                                                             \
        *(uint4*)(sm2 + (SUMB) + e_ * 272 + cq_ * 16) = so_;                          \
        *(uint4*)(sm2 + (DIFB) + e_ * 272 + cq_ * 16) = do_;                          \
    }
#define PSTP_A(SUMB, DIFB, IT) PSTP_X(SUMB, DIFB, IT, ha_, hb_)
#define PSTP_B(SUMB, DIFB, IT) PSTP_X(SUMB, DIFB, IT, hc_, hd_)

#define MMA_STEP(ABASE, BBASE, KBA, KBB)                                              \
    {                                                                                 \
        uint32_t ah_[4][4], bb_[2][4];                                                \
        _Pragma("unroll") for (int mi = 0; mi < 4; mi++)                              \
            ldsm4(ah_[mi], sb + (ABASE) + aOff + mi * (16 * 144) + (KBA));            \
        _Pragma("unroll") for (int p = 0; p < 2; p++)                                 \
            ldsm4(bb_[p], sb + (BBASE) + bOff + p * (16 * 272) + (KBB));              \
        _Pragma("unroll") for (int mi = 0; mi < 4; mi++)                              \
            _Pragma("unroll") for (int ni = 0; ni < 4; ni++)                          \
                mma_f16(acc[mi][ni], ah_[mi], &bb_[ni >> 1][(ni & 1) * 2]);           \
    }

    // ---- prologue: A(feat0,kh0)->A0; nidx; self tile -> BA via cp.async ----
    CPA_A(0, 0, SM_A0);
    if (tid < 128) nidx[tid] = ((const int4*)gemm)[(size_t)b * NE + e0 + tid];
#pragma unroll
    for (int it = 0; it < 4; it++) {
        int ii = tid + it * 512;
        int e = ii >> 4, cq = ii & 15;
        CPA(sb + SM_BA + e * 272 + cq * 16, XtH + (size_t)(e0 + e) * 128 + cq * 8);
    }
    CPA_COMMIT();
    CPA_WAIT();
    __syncthreads();

#define PHASE(PRE, BBASE, KH, G0, G1, G2, G3)                                         \
    PRE                                                                               \
    G0                                                                                \
    MMA_STEP((KH) ? SM_A1 : SM_A0, BBASE, 0, ((KH) * 4 + 0) * 32);                    \
    MMA_STEP((KH) ? SM_A1 : SM_A0, BBASE, 32, ((KH) * 4 + 1) * 32);                   \
    G1 G2                                                                             \
    MMA_STEP((KH) ? SM_A1 : SM_A0, BBASE, 64, ((KH) * 4 + 2) * 32);                   \
    MMA_STEP((KH) ? SM_A1 : SM_A0, BBASE, 96, ((KH) * 4 + 3) * 32);                   \
    G3                                                                                \
    CPA_WAIT();                                                                       \
    __syncthreads();

    // P1-P2: self (W0); gather pair0 -> BB(sum), BC(diff); deferred stores
    PHASE(CPA_A(0, 1, SM_A1);, SM_BA, 0,
          LDGP_A(0, 0); LDGP_B(0, 1);, ;, ;, PSTP_A(SM_BB, SM_BC, 0);)
    PHASE(CPA_A(1, 0, SM_A0);, SM_BA, 1,
          PSTP_B(SM_BB, SM_BC, 1); LDGP_A(0, 2); LDGP_B(0, 3);, ;,
          PSTP_A(SM_BB, SM_BC, 2);, PSTP_B(SM_BB, SM_BC, 3);)
    // P3-P4: sum0 (W1); gather pair1 -> BD(sum), BA(diff)
    PHASE(CPA_A(1, 1, SM_A1);, SM_BB, 0,
          LDGP_A(1, 0); LDGP_B(1, 1);, ;, ;, PSTP_A(SM_BD, SM_BA, 0);)
    PHASE(CPA_A(3, 0, SM_A0);, SM_BB, 1,
          PSTP_B(SM_BD, SM_BA, 1); LDGP_A(1, 2); LDGP_B(1, 3);, ;,
          PSTP_A(SM_BD, SM_BA, 2);, PSTP_B(SM_BD, SM_BA, 3);)
    // P5-P6: diff0 (W3)
    PHASE(CPA_A(3, 1, SM_A1);, SM_BC, 0, ;, ;, ;, ;)
    PHASE(CPA_A(2, 0, SM_A0);, SM_BC, 1, ;, ;, ;, ;)
    // P7-P8: sum1 (W2)
    PHASE(CPA_A(2, 1, SM_A1);, SM_BD, 0, ;, ;, ;, ;)
    PHASE(CPA_A(4, 0, SM_A0);, SM_BD, 1, ;, ;, ;, ;)
    // P9-P10: diff1 (W4, in BA)
    PHASE(CPA_A(4, 1, SM_A1);, SM_BA, 0, ;, ;, ;, ;)
    PHASE(;, SM_BA, 1, ;, ;, ;, ;)

    // ---- epilogue: bias + fp16 store + row stats ----
    float* sAcc = (float*)sm2;
    for (int i = tid; i < 512; i += 512) sAcc[i] = 0.f;
    __syncthreads();

    int rbase = z * 256 + wm * 64;
    int colLocal = wn * 32 + (lane & 3) * 2;
#pragma unroll
    for (int mi = 0; mi < 4; mi++) {
        int r0 = rbase + mi * 16 + (lane >> 2);
        int r1 = r0 + 8;
        float c0 = g_Cf[r0], c1 = g_Cf[r1];
        __half* d0 = g_preH + ((size_t)b * 512 + r0) * NE + e0 + colLocal;
        __half* d1 = g_preH + ((size_t)b * 512 + r1) * NE + e0 + colLocal;
        float s0 = 0.f, q0 = 0.f, s1 = 0.f, q1 = 0.f;
#pragma unroll
        for (int ni = 0; ni < 4; ni++) {
            float v00 = acc[mi][ni][0] + c0, v01 = acc[mi][ni][1] + c0;
            float v10 = acc[mi][ni][2] + c1, v11 = acc[mi][ni][3] + c1;
            *(__half2*)(d0 + ni * 8) = __floats2half2_rn(v00, v01);
            *(__half2*)(d1 + ni * 8) = __floats2half2_rn(v10, v11);
            s0 += v00 + v01; q0 += v00 * v00 + v01 * v01;
            s1 += v10 + v11; q1 += v10 * v10 + v11 * v11;
        }
#pragma unroll
        for (int o = 1; o <= 2; o <<= 1) {
            s0 += __shfl_xor_sync(0xFFFFFFFFu, s0, o);
            q0 += __shfl_xor_sync(0xFFFFFFFFu, q0, o);
            s1 += __shfl_xor_sync(0xFFFFFFFFu, s1, o);
            q1 += __shfl_xor_sync(0xFFFFFFFFu, q1, o);
        }
        if ((lane & 3) == 0) {
            int rl0 = wm * 64 + mi * 16 + (lane >> 2);
            atomicAdd(&sAcc[rl0 * 2], s0);
            atomicAdd(&sAcc[rl0 * 2 + 1], q0);
            atomicAdd(&sAcc[(rl0 + 8) * 2], s1);
            atomicAdd(&sAcc[(rl0 + 8) * 2 + 1], q1);
        }
    }
    __syncthreads();
    for (int i = tid; i < 512; i += 512) {
        int rowl = i >> 1;
        int gidx = b * 512 + z * 256 + rowl;
        if (i & 1) atomicAdd(&g_S2[gidx], sAcc[i]);
        else       atomicAdd(&g_S[gidx], sAcc[i]);
    }
}

// ---------------- kernel 4: fused norm + sigmoid + softmax blend (stats inlined) -----------
__global__ __launch_bounds__(256) void final_kernel(const float* __restrict__ x0,
                                                    const float* __restrict__ x1,
                                                    float* __restrict__ out) {
    size_t idx = (size_t)blockIdx.x * 256 + threadIdx.x;
    int e4 = (int)(idx & (NE / 4 - 1));
    int c = (int)((idx >> 14) & 255);
    int b = (int)(idx >> 22);

    uint2 pau = *(const uint2*)&g_preH[((size_t)b * 512 + c) * NE + e4 * 4];
    uint2 pbu = *(const uint2*)&g_preH[((size_t)b * 512 + 256 + c) * NE + e4 * 4];
    float2 pa01 = __half22float2(*(__half2*)&pau.x);
    float2 pa23 = __half22float2(*(__half2*)&pau.y);
    float2 pb01 = __half22float2(*(__half2*)&pbu.x);
    float2 pb23 = __half22float2(*(__half2*)&pbu.y);
    float4 pa = make_float4(pa01.x, pa01.y, pa23.x, pa23.y);
    float4 pb = make_float4(pb01.x, pb01.y, pb23.x, pb23.y);
    float4 a0 = ((const float4*)x0)[idx];
    float4 a1 = ((const float4*)x1)[idx];

    int ia = b * 512 + c, ib = b * 512 + 256 + c;
    float ma = g_S[ia] * (1.f / (float)NE);
    float ra = rsqrtf(g_S2[ia] * (1.f / (float)NE) - ma * ma + 1e-5f);
    float mb = g_S[ib] * (1.f / (float)NE);
    float rb = rsqrtf(g_S2[ib] * (1.f / (float)NE) - mb * mb + 1e-5f);

    float4 o;
#define BLEND(fld)                                              \
    {                                                           \
        float za = (pa.fld - ma) * ra;                          \
        float zb = (pb.fld - mb) * rb;                          \
        float wa = 1.f / (1.f + expf(-za));                     \
        float wb = 1.f / (1.f + expf(-zb));                     \
        float w0 = 1.f / (1.f + expf(wb - wa));                 \
        o.fld = a0.fld * w0 + a1.fld * (1.f - w0);              \
    }
    BLEND(x); BLEND(y); BLEND(z); BLEND(w);
#undef BLEND
    ((float4*)out)[idx] = o;
}

// ---------------- launch ----------------
extern "C" void kernel_launch(void* const* d_in, const int* in_sizes, int n_in,
                              void* d_out, int out_size) {
    const float* x0  = (const float*)d_in[0];
    const float* x1  = (const float*)d_in[1];
    const int*   gm  = (const int*)d_in[2];
    const float* Wa  = (const float*)d_in[3];
    const float* ba  = (const float*)d_in[4];
    const float* Wb  = (const float*)d_in[5];
    const float* bb  = (const float*)d_in[6];
    const float* Wal = (const float*)d_in[7];
    const float* bal = (const float*)d_in[8];
    const float* Wbl = (const float*)d_in[9];
    const float* bbl = (const float*)d_in[10];
    const float* Wat = (const float*)d_in[11];
    const float* bat = (const float*)d_in[12];
    const float* Wbt = (const float*)d_in[13];
    const float* bbt = (const float*)d_in[14];
    const float* Waf = (const float*)d_in[15];
    const float* baf = (const float*)d_in[16];
    const float* Wbf = (const float*)d_in[17];
    const float* bbf = (const float*)d_in[18];
    float* out = (float*)d_out;

    conv_w1_kernel<<<128, 256>>>(Wa, Wb);
    fold_w_kernel<<<512, 128>>>(Waf, Wal, Wat, Wbf, Wbl, Wbt);
    fold_c_kernel<<<512, 128>>>(Waf, bal, bat, baf, Wbf, bbl, bbt, bbf);

    cudaFuncSetAttribute(stage1_kernel, cudaFuncAttributeMaxDynamicSharedMemorySize, S1_TOT);
    stage1_kernel<<<dim3(NE / 128, NB, 2), 256, S1_TOT>>>(x0, x1, ba, bb);

    cudaFuncSetAttribute(stage2_kernel, cudaFuncAttributeMaxDynamicSharedMemorySize, SM_TOT);
    stage2_kernel<<<dim3(NE / 128, NB, 2), 512, SM_TOT>>>(gm);

    final_kernel<<<(NB * 256 * (NE / 4)) / 256, 256>>>(x0, x1, out);
}